// round 13
// baseline (speedup 1.0000x reference)
#include <cuda_runtime.h>
#include <math.h>

// Problem constants
#define NMAT 16384
#define P 33                  // pitch for the tiny single-warp kernels only
#define NWARPS 4              // warps per block in batched kernels
#define NBLK2 (NMAT / 8)      // 2048 blocks: 4 warps x 2 packed matrices
#define SWEEPS_BATCH 5
#define SWEEPS_SINGLE 7

typedef unsigned long long u64;

// ---------------- device scratch (static globals: allowed) ----------------
__device__ float g_part[64 * 1024];
__device__ float g_bm_sq[1024];
__device__ float g_isq[1024];
__device__ float g_GT_part[(size_t)NBLK2 * 1024];  // 8 MB
__device__ float g_Linv[1024];
__device__ float g_LinvT[1024];
__device__ float g_Lw[1024];
__device__ float g_LwT[1024];
__device__ float g_vcT[(size_t)NMAT * 1024];       // 64 MB, transposed [k][i]
__device__ float g_logw[NMAT * 32];
__device__ float g_dist_part[NBLK2];
__device__ float g_factor[1];

// ---------------- packed f32x2 helpers ----------------
__device__ __forceinline__ u64 pk(float x, float y) {
    u64 r; asm("mov.b64 %0,{%1,%2};" : "=l"(r) : "f"(x), "f"(y)); return r;
}
__device__ __forceinline__ void upk(u64 p, float& x, float& y) {
    asm("mov.b64 {%0,%1},%2;" : "=f"(x), "=f"(y) : "l"(p));
}
__device__ __forceinline__ u64 fma2(u64 a, u64 b, u64 c) {
    u64 d; asm("fma.rn.f32x2 %0,%1,%2,%3;" : "=l"(d) : "l"(a), "l"(b), "l"(c)); return d;
}
__device__ __forceinline__ u64 mul2(u64 a, u64 b) {
    u64 d; asm("mul.rn.f32x2 %0,%1,%2;" : "=l"(d) : "l"(a), "l"(b)); return d;
}
__device__ __forceinline__ u64 add2(u64 a, u64 b) {
    u64 d; asm("add.rn.f32x2 %0,%1,%2;" : "=l"(d) : "l"(a), "l"(b)); return d;
}

// ---------------- packed dual-matrix Jacobi (XOR ordering) ----------------
// Thread `lane` holds column `lane` of TWO symmetric matrices in a[0..31]
// (lo = matrix 0, hi = matrix 1) and row `lane` of both V's in v[0..31].
// Returns packed eigenvalues for eigenvector column `lane`.
__device__ __forceinline__ u64 eig_pk(u64 a[32], u64 v[32],
                                      u64* ccA, u64* ssA, u64* msA,
                                      int lane, int sweeps) {
    const unsigned FULL = 0xffffffffu;
    const u64 ONE2 = pk(1.f, 1.f), ZERO2 = pk(0.f, 0.f), HALF2 = pk(0.5f, 0.5f);
#pragma unroll
    for (int i = 0; i < 32; i++) v[i] = (i == lane) ? ONE2 : ZERO2;
    u64 diag2 = a[0], apq2 = a[1];
    int p1 = lane ^ 1;
#pragma unroll
    for (int k = 0; k < 32; k++) {
        diag2 = (k == lane) ? a[k] : diag2;
        apq2  = (k == p1)   ? a[k] : apq2;
    }
    for (int sw = 0; sw < sweeps; sw++) {
#pragma unroll
        for (int m = 1; m < 32; m++) {
            int t0i = m; t0i |= t0i >> 1; t0i |= t0i >> 2; t0i |= t0i >> 4;
            const int lmask = t0i >> 1;
            const int mn = (m == 31) ? 1 : (m + 1);
            bool is_lo = lane < (lane ^ m);
            // --- rotation (scalar per half; both lanes of pair identical) ---
            u64 apq_sh = __shfl_xor_sync(FULL, apq2, m);
            u64 apq_s2 = mul2(HALF2, add2(apq2, apq_sh));
            u64 dp2 = __shfl_xor_sync(FULL, diag2, m);
            u64 app2 = is_lo ? diag2 : dp2;
            u64 aqq2 = is_lo ? dp2 : diag2;
            float as0, as1, ap0, ap1, aq0, aq1;
            upk(apq_s2, as0, as1); upk(app2, ap0, ap1); upk(aqq2, aq0, aq1);
            float th0 = __fdividef(aq0 - ap0, 2.f * as0);
            float th1 = __fdividef(aq1 - ap1, 2.f * as1);
            float q0 = fmaf(th0, th0, 1.f), q1 = fmaf(th1, th1, 1.f);
            float sq0 = q0 * rsqrtf(q0),    sq1 = q1 * rsqrtf(q1);
            float tt0 = __fdividef(copysignf(1.f, th0), fabsf(th0) + sq0);
            float tt1 = __fdividef(copysignf(1.f, th1), fabsf(th1) + sq1);
            float te0 = (fabsf(as0) > 1e-12f) ? tt0 : 0.f;
            float te1 = (fabsf(as1) > 1e-12f) ? tt1 : 0.f;
            float c0 = rsqrtf(fmaf(te0, te0, 1.f));
            float c1 = rsqrtf(fmaf(te1, te1, 1.f));
            float s0 = te0 * c0, s1 = te1 * c1;
            u64 c2  = pk(c0, c1);
            u64 s2  = pk(s0, s1);
            u64 ms2 = pk(-s0, -s1);
            u64 t2  = pk(te0, te1);
            u64 mt2 = pk(-te0, -te1);
            u64 tsig = is_lo ? mt2 : t2;
            diag2 = fma2(tsig, apq_s2, diag2);       // analytic diag update
            u64 ssg = is_lo ? ms2 : s2;
            u64 cg  = c2;
            ccA[lane] = c2; ssA[lane] = s2; msA[lane] = ms2;
            __syncwarp();
            // --- row phase on A + V (register-local, packed) ---
#pragma unroll
            for (int k = 0; k < 16; k++) {
                const int i = ((k & ~lmask) << 1) | (k & lmask);
                const int j = i ^ m;
                u64 cc = ccA[i], ss = ssA[i], ms = msA[i];
                u64 ai = a[i], aj = a[j];
                a[i] = fma2(cc, ai, mul2(ms, aj));
                a[j] = fma2(ss, ai, mul2(cc, aj));
                u64 vi = v[i], vj = v[j];
                v[i] = fma2(cc, vi, mul2(ms, vj));
                v[j] = fma2(ss, vi, mul2(cc, vj));
            }
            // --- cross-thread column mix of A + apq tracking ---
            u64 napq = apq2;
            int pn = lane ^ mn;
#pragma unroll
            for (int k = 0; k < 32; k++) {
                u64 ax = __shfl_xor_sync(FULL, a[k], m);
                a[k] = fma2(ssg, ax, mul2(cg, a[k]));
                napq = (k == pn) ? a[k] : napq;
            }
            apq2 = napq;
        }
    }
    return diag2;
}

// acc[0..31] = column `lane` of (A @ B) for both packed matrices.
// A: 1024 u64 in shared (row-major, packed pair per element, 16B aligned).
// b[k] = packed B[k][lane].
__device__ __forceinline__ void gemm2(const u64* __restrict__ A,
                                      const u64 b[32], u64 acc[32]) {
    const ulonglong2* A2 = reinterpret_cast<const ulonglong2*>(A);
#pragma unroll
    for (int i = 0; i < 32; i++) {
        ulonglong2 av = A2[i * 16];
        u64 s = mul2(av.x, b[0]);
        s = fma2(av.y, b[1], s);
#pragma unroll
        for (int k2 = 1; k2 < 16; k2++) {
            av = A2[i * 16 + k2];
            s = fma2(av.x, b[2 * k2], s);
            s = fma2(av.y, b[2 * k2 + 1], s);
        }
        acc[i] = s;
    }
}

// ---------------- scalar Jacobi + helpers for tiny single-warp kernels ----
__device__ __forceinline__ float warp_eig_sym_reg(float a[32], float v[32],
                                                  float2* cs2, int lane, int sweeps) {
    const unsigned FULL = 0xffffffffu;
#pragma unroll
    for (int i = 0; i < 32; i++) v[i] = (i == lane) ? 1.f : 0.f;
    float diag = 0.f, apq = 0.f;
    int p1 = lane ^ 1;
#pragma unroll
    for (int k = 0; k < 32; k++) {
        diag = (k == lane) ? a[k] : diag;
        apq  = (k == p1)   ? a[k] : apq;
    }
    for (int sw = 0; sw < sweeps; sw++) {
#pragma unroll
        for (int m = 1; m < 32; m++) {
            int t0 = m; t0 |= t0 >> 1; t0 |= t0 >> 2; t0 |= t0 >> 4;
            const int lmask = t0 >> 1;
            const int mn = (m == 31) ? 1 : (m + 1);
            bool is_lo = lane < (lane ^ m);
            float apq_s = 0.5f * (apq + __shfl_xor_sync(FULL, apq, m));
            float dp  = __shfl_xor_sync(FULL, diag, m);
            float app = is_lo ? diag : dp;
            float aqq = is_lo ? dp : diag;
            float th  = (aqq - app) / (2.f * apq_s);
            float tt  = copysignf(1.f, th) / (fabsf(th) + sqrtf(fmaf(th, th, 1.f)));
            float t_eff = (fabsf(apq_s) > 1e-12f) ? tt : 0.f;
            float c = rsqrtf(fmaf(t_eff, t_eff, 1.f));
            float s = t_eff * c;
            float s_signed = is_lo ? -s : s;
            float t_signed = is_lo ? -t_eff : t_eff;
            diag = fmaf(t_signed, apq_s, diag);
            cs2[lane] = make_float2(c, s);
            __syncwarp();
#pragma unroll
            for (int k = 0; k < 16; k++) {
                const int i = ((k & ~lmask) << 1) | (k & lmask);
                const int j = i ^ m;
                float2 cs = cs2[i];
                float ci = cs.x, si = cs.y;
                float x = a[i], y = a[j];
                a[i] = ci * x - si * y;
                a[j] = si * x + ci * y;
                float vx = v[i], vy = v[j];
                v[i] = ci * vx - si * vy;
                v[j] = si * vx + ci * vy;
            }
            float napq = apq;
            int pn = lane ^ mn;
#pragma unroll
            for (int k = 0; k < 32; k++) {
                float ax = __shfl_xor_sync(FULL, a[k], m);
                a[k] = fmaf(s_signed, ax, c * a[k]);
                napq = (k == pn) ? a[k] : napq;
            }
            apq = napq;
        }
    }
    return diag;
}

__device__ __forceinline__ void wmm(const float* A, const float* B, float* C, int lane) {
    __syncwarp();
    float col[32];
#pragma unroll
    for (int i = 0; i < 32; i++) col[i] = 0.f;
#pragma unroll 4
    for (int k = 0; k < 32; k++) {
        float b = B[k * P + lane];
#pragma unroll
        for (int i = 0; i < 32; i++) col[i] = fmaf(A[i * P + k], b, col[i]);
    }
    __syncwarp();
#pragma unroll
    for (int i = 0; i < 32; i++) C[i * P + lane] = col[i];
    __syncwarp();
}

__device__ void warp_chol(float* A, int lane) {
    for (int j = 0; j < 32; j++) {
        if (lane == 0) A[j * P + j] = sqrtf(A[j * P + j]);
        __syncwarp();
        float d = A[j * P + j];
        if (lane > j) A[lane * P + j] /= d;
        __syncwarp();
        float ll = (lane > j) ? A[lane * P + j] : 0.f;
        for (int k = j + 1; k < 32; k++) {
            float lkj = A[k * P + j];
            if (lane >= k) A[lane * P + k] -= ll * lkj;
        }
        __syncwarp();
    }
}

__device__ void warp_trisolve(const float* L, float* Y, int lane) {
    for (int i = 0; i < 32; i++) {
        float rhs = (i == lane) ? 1.f : 0.f;
        for (int k = 0; k < i; k++) rhs -= L[i * P + k] * Y[k * P + lane];
        Y[i * P + lane] = rhs / L[i * P + i];
        __syncwarp();
    }
}

// ---------------- K1: partial sums for bm ----------------
__global__ void __launch_bounds__(1024) k1_bm_partial(const float* __restrict__ X) {
    int tid = threadIdx.x;
    const float* base = X + (size_t)blockIdx.x * 256 * 1024 + tid;
    float s = 0.f;
#pragma unroll 4
    for (int b = 0; b < 256; b++) s += base[(size_t)b * 1024];
    g_part[blockIdx.x * 1024 + tid] = s;
}

// ---------------- K2: bm eigh -> bm^{1/2}, bm^{-1/2} (ONE WARP) ----------------
__global__ void __launch_bounds__(32) k2_bm_sqrt() {
    __shared__ float V[32 * P], g[32];
    __shared__ float2 cs2[32];
    int lane = threadIdx.x;
    float a[32], v[32];
#pragma unroll
    for (int i = 0; i < 32; i++) {
        float s = 0.f;
        for (int blk = 0; blk < 64; blk++) s += g_part[blk * 1024 + i * 32 + lane];
        a[i] = s * (1.f / (float)NMAT);
    }
    float diag = warp_eig_sym_reg(a, v, cs2, lane, SWEEPS_SINGLE);
#pragma unroll
    for (int k = 0; k < 32; k++) V[lane * P + k] = v[k];
    g[lane] = sqrtf(diag);
    __syncwarp();
    {
        float col[32];
#pragma unroll
        for (int i = 0; i < 32; i++) col[i] = 0.f;
        for (int k = 0; k < 32; k++) {
            float b = g[k] * V[lane * P + k];
#pragma unroll
            for (int i = 0; i < 32; i++) col[i] = fmaf(V[i * P + k], b, col[i]);
        }
#pragma unroll
        for (int i = 0; i < 32; i++) g_bm_sq[i * 32 + lane] = col[i];
    }
    {
        float col[32];
#pragma unroll
        for (int i = 0; i < 32; i++) col[i] = 0.f;
        for (int k = 0; k < 32; k++) {
            float b = V[lane * P + k] / g[k];
#pragma unroll
            for (int i = 0; i < 32; i++) col[i] = fmaf(V[i * P + k], b, col[i]);
        }
#pragma unroll
        for (int i = 0; i < 32; i++) g_isq[i * 32 + lane] = col[i];
    }
}

// ---------------- K3: XT = log(isq X isq), partial GT sums (packed x2) -------
__global__ void __launch_bounds__(128, 3) k3_logmean(const float* __restrict__ X) {
    __shared__ __align__(16) u64 shBD[1024];           // duplicated isq
    __shared__ __align__(16) u64 buf[NWARPS][1024];    // X2 -> S2 -> VT2 -> acc2
    __shared__ u64 ccA[NWARPS][32], ssA[NWARPS][32], msA[NWARPS][32];
    __shared__ u64 shG2[NWARPS][32];
    int tid = threadIdx.x, warp = tid >> 5, lane = tid & 31;
    for (int e = tid; e < 1024; e += 128) { float x = g_isq[e]; shBD[e] = pk(x, x); }
    __syncthreads();

    u64* bw = buf[warp];
    int b0 = (blockIdx.x * NWARPS + warp) * 2;
    const float* X0 = X + (size_t)b0 * 1024;
#pragma unroll
    for (int i = 0; i < 32; i++)
        bw[i * 32 + lane] = pk(X0[i * 32 + lane], X0[1024 + i * 32 + lane]);
    __syncwarp();

    // S = X @ isq
    u64 breg[32], acc[32];
#pragma unroll
    for (int k = 0; k < 32; k++) breg[k] = shBD[k * 32 + lane];
    gemm2(bw, breg, acc);
    __syncwarp();
#pragma unroll
    for (int i = 0; i < 32; i++) bw[i * 32 + lane] = acc[i];
    __syncwarp();

    // inner = isq @ S
    u64 a2[32], v2[32];
#pragma unroll
    for (int k = 0; k < 32; k++) breg[k] = bw[k * 32 + lane];
    gemm2(shBD, breg, a2);

    u64 diag2 = eig_pk(a2, v2, ccA[warp], ssA[warp], msA[warp], lane, SWEEPS_BATCH);
    float d0, d1; upk(diag2, d0, d1);
    shG2[warp][lane] = pk(logf(d0), logf(d1));
#pragma unroll
    for (int k = 0; k < 32; k++) bw[k * 32 + lane] = v2[k];   // VT packed
    __syncwarp();

    // XT column lane: acc[i] = sum_k VT[k][i] * (logw_k * v[k])   (both mats)
    const u64 Z = pk(0.f, 0.f);
#pragma unroll
    for (int i = 0; i < 32; i++) acc[i] = Z;
#pragma unroll
    for (int k = 0; k < 32; k++) {
        u64 bb = mul2(shG2[warp][k], v2[k]);
        const ulonglong2* R = reinterpret_cast<const ulonglong2*>(bw + k * 32);
#pragma unroll
        for (int i2 = 0; i2 < 16; i2++) {
            ulonglong2 rr = R[i2];
            acc[2 * i2]     = fma2(rr.x, bb, acc[2 * i2]);
            acc[2 * i2 + 1] = fma2(rr.y, bb, acc[2 * i2 + 1]);
        }
    }
    // park packed XT, then deterministic slice-parallel reduce + half fold
#pragma unroll
    for (int i = 0; i < 32; i++) bw[i * 32 + lane] = acc[i];
    __syncthreads();
#pragma unroll
    for (int r = 0; r < 8; r++) {
        int row = warp * 8 + r;
        u64 s0 = buf[0][row * 32 + lane];
        u64 s1 = buf[1][row * 32 + lane];
        u64 s2 = buf[2][row * 32 + lane];
        u64 s3 = buf[3][row * 32 + lane];
        u64 t = add2(add2(add2(s0, s1), s2), s3);
        float lo, hi; upk(t, lo, hi);
        g_GT_part[(size_t)blockIdx.x * 1024 + row * 32 + lane] = lo + hi;
    }
}

// ---------------- K4a: fold 2048 GT partials -> 64 (into g_part) -------------
__global__ void __launch_bounds__(1024) k4a_reduce() {
    int tid = threadIdx.x;
    int blk = blockIdx.x;  // 0..63
    float s = 0.f;
#pragma unroll 4
    for (int j = 0; j < 32; j++)
        s += g_GT_part[(size_t)(blk * 32 + j) * 1024 + tid];
    g_part[blk * 1024 + tid] = s;
}

// ---------------- K4: GT -> batch_mean -> Linv/LinvT; Lw/LwT (ONE WARP) ------
__global__ void __launch_bounds__(32) k4_center(const float* __restrict__ weight) {
    __shared__ float A[32 * P], V[32 * P], M[32 * P], S[32 * P], T[32 * P], g[32];
    __shared__ float2 cs2[32];
    int lane = threadIdx.x;
    float a[32], v[32];
#pragma unroll
    for (int i = 0; i < 32; i++) {
        float s = 0.f;
        for (int blk = 0; blk < 64; blk++) s += g_part[blk * 1024 + i * 32 + lane];
        a[i] = s * (1.f / (float)NMAT);
    }
    float diag = warp_eig_sym_reg(a, v, cs2, lane, SWEEPS_SINGLE);
#pragma unroll
    for (int k = 0; k < 32; k++) V[lane * P + k] = v[k];
    g[lane] = expf(diag);
    __syncwarp();
    {
        float col[32];
#pragma unroll
        for (int i = 0; i < 32; i++) col[i] = 0.f;
        for (int k = 0; k < 32; k++) {
            float b = g[k] * V[lane * P + k];
#pragma unroll
            for (int i = 0; i < 32; i++) col[i] = fmaf(V[i * P + k], b, col[i]);
        }
#pragma unroll
        for (int i = 0; i < 32; i++) M[i * P + lane] = col[i];
    }
    __syncwarp();
#pragma unroll
    for (int i = 0; i < 32; i++) S[i * P + lane] = g_bm_sq[i * 32 + lane];
    __syncwarp();
    wmm(S, M, T, lane);
    wmm(T, S, A, lane);          // A = batch_mean
    warp_chol(A, lane);
    warp_trisolve(A, T, lane);   // T = L^{-1}
#pragma unroll
    for (int i = 0; i < 32; i++) {
        float lv  = (lane <= i) ? T[i * P + lane] : 0.f;
        g_Linv[i * 32 + lane] = lv;
        float lvt = (i <= lane) ? T[lane * P + i] : 0.f;
        g_LinvT[i * 32 + lane] = lvt;
    }
#pragma unroll
    for (int i = 0; i < 32; i++) M[i * P + lane] = weight[i * 32 + lane];
    __syncwarp();
    warp_chol(M, lane);
#pragma unroll
    for (int i = 0; i < 32; i++) {
        float lv  = (lane <= i) ? M[i * P + lane] : 0.f;
        g_Lw[i * 32 + lane] = lv;
        float lvt = (i <= lane) ? M[lane * P + i] : 0.f;
        g_LwT[i * 32 + lane] = lvt;
    }
}

// ---------------- K5: Xc eig (packed x2), store vcT/logw, variance -----------
__global__ void __launch_bounds__(128, 3) k5_center_eig(const float* __restrict__ X) {
    __shared__ __align__(16) u64 shAD[1024];            // Linv duplicated
    __shared__ __align__(16) float shBT[1024];          // LinvT scalar
    __shared__ __align__(16) u64 buf[NWARPS][1024];
    __shared__ u64 ccA[NWARPS][32], ssA[NWARPS][32], msA[NWARPS][32];
    __shared__ float shRed[NWARPS];
    int tid = threadIdx.x, warp = tid >> 5, lane = tid & 31;
    for (int e = tid; e < 1024; e += 128) {
        float x = g_Linv[e]; shAD[e] = pk(x, x);
        shBT[e] = g_LinvT[e];
    }
    __syncthreads();

    u64* bw = buf[warp];
    int b0 = (blockIdx.x * NWARPS + warp) * 2;
    const float* X0 = X + (size_t)b0 * 1024;
#pragma unroll
    for (int i = 0; i < 32; i++)
        bw[i * 32 + lane] = pk(X0[i * 32 + lane], X0[1024 + i * 32 + lane]);
    __syncwarp();

    // S = X @ Linv^T
    u64 breg[32], acc[32];
#pragma unroll
    for (int k = 0; k < 32; k++) { float x = shBT[k * 32 + lane]; breg[k] = pk(x, x); }
    gemm2(bw, breg, acc);
    __syncwarp();
#pragma unroll
    for (int i = 0; i < 32; i++) bw[i * 32 + lane] = acc[i];
    __syncwarp();

    // Xc = Linv @ S
    u64 a2[32], v2[32];
#pragma unroll
    for (int k = 0; k < 32; k++) breg[k] = bw[k * 32 + lane];
    gemm2(shAD, breg, a2);

    u64 diag2 = eig_pk(a2, v2, ccA[warp], ssA[warp], msA[warp], lane, SWEEPS_BATCH);

    // store eigenvectors transposed, both matrices, straight from registers
    float* vt = g_vcT + (size_t)b0 * 1024;
#pragma unroll
    for (int k = 0; k < 32; k++) {
        float x, y; upk(v2[k], x, y);
        vt[k * 32 + lane] = x;
        vt[1024 + k * 32 + lane] = y;
    }
    float d0, d1; upk(diag2, d0, d1);
    float lw0 = logf(d0), lw1 = logf(d1);
    g_logw[b0 * 32 + lane] = lw0;
    g_logw[(b0 + 1) * 32 + lane] = lw1;

    float d = lw0 * lw0 + lw1 * lw1;
#pragma unroll
    for (int off = 16; off; off >>= 1) d += __shfl_xor_sync(0xffffffffu, d, off);
    if (lane == 0) shRed[warp] = d;
    __syncthreads();
    if (tid == 0) {
        float t = 0.f;
        for (int w = 0; w < NWARPS; w++) t += shRed[w];
        g_dist_part[blockIdx.x] = t;
    }
}

// ---------------- K6: scalar factor ----------------
__global__ void __launch_bounds__(256) k6_factor(const float* __restrict__ shift) {
    __shared__ float sh[256];
    int tid = threadIdx.x;
    float s = 0.f;
    for (int i = tid; i < NBLK2; i += 256) s += g_dist_part[i];
    sh[tid] = s;
    __syncthreads();
    for (int st = 128; st; st >>= 1) {
        if (tid < st) sh[tid] += sh[tid + st];
        __syncthreads();
    }
    if (tid == 0) {
        float var = sh[0] * (1.f / (float)NMAT);
        g_factor[0] = shift[0] / sqrtf(var + 1e-5f);
    }
}

// ---------------- K7: Xs = vc e^{f logw} vc^T; out = Lw Xs Lw^T (packed x2) --
__global__ void __launch_bounds__(128, 3) k7_output(float* __restrict__ out) {
    __shared__ __align__(16) u64 shAD[1024];            // Lw duplicated
    __shared__ __align__(16) float shBT[1024];          // LwT scalar
    __shared__ __align__(16) u64 buf[NWARPS][1024];
    __shared__ u64 shG2[NWARPS][32];
    int tid = threadIdx.x, warp = tid >> 5, lane = tid & 31;
    for (int e = tid; e < 1024; e += 128) {
        float x = g_Lw[e]; shAD[e] = pk(x, x);
        shBT[e] = g_LwT[e];
    }
    __syncthreads();

    u64* bw = buf[warp];
    int b0 = (blockIdx.x * NWARPS + warp) * 2;
    float factor = g_factor[0];
    const float* vt = g_vcT + (size_t)b0 * 1024;
    u64 v2[32];
#pragma unroll
    for (int k = 0; k < 32; k++) {
        u64 p = pk(vt[k * 32 + lane], vt[1024 + k * 32 + lane]);
        bw[k * 32 + lane] = p;
        v2[k] = p;
    }
    shG2[warp][lane] = pk(expf(factor * g_logw[b0 * 32 + lane]),
                          expf(factor * g_logw[(b0 + 1) * 32 + lane]));
    __syncwarp();

    // Xs column lane
    u64 acc[32];
    const u64 Z = pk(0.f, 0.f);
#pragma unroll
    for (int i = 0; i < 32; i++) acc[i] = Z;
#pragma unroll
    for (int k = 0; k < 32; k++) {
        u64 bb = mul2(shG2[warp][k], v2[k]);
        const ulonglong2* R = reinterpret_cast<const ulonglong2*>(bw + k * 32);
#pragma unroll
        for (int i2 = 0; i2 < 16; i2++) {
            ulonglong2 rr = R[i2];
            acc[2 * i2]     = fma2(rr.x, bb, acc[2 * i2]);
            acc[2 * i2 + 1] = fma2(rr.y, bb, acc[2 * i2 + 1]);
        }
    }
    __syncwarp();
#pragma unroll
    for (int i = 0; i < 32; i++) bw[i * 32 + lane] = acc[i];  // buf = Xs
    __syncwarp();

    // W = Xs @ Lw^T
    u64 breg[32];
#pragma unroll
    for (int k = 0; k < 32; k++) { float x = shBT[k * 32 + lane]; breg[k] = pk(x, x); }
    gemm2(bw, breg, acc);
    __syncwarp();
#pragma unroll
    for (int i = 0; i < 32; i++) bw[i * 32 + lane] = acc[i];  // buf = W
    __syncwarp();

    // out = Lw @ W
#pragma unroll
    for (int k = 0; k < 32; k++) breg[k] = bw[k * 32 + lane];
    gemm2(shAD, breg, acc);

    float* ob = out + (size_t)b0 * 1024;
#pragma unroll
    for (int i = 0; i < 32; i++) {
        float x, y; upk(acc[i], x, y);
        ob[i * 32 + lane] = x;
        ob[1024 + i * 32 + lane] = y;
    }
}

// ---------------- launch ----------------
extern "C" void kernel_launch(void* const* d_in, const int* in_sizes, int n_in,
                              void* d_out, int out_size) {
    (void)in_sizes; (void)n_in; (void)out_size;
    const float* X = (const float*)d_in[0];
    const float* weight = (const float*)d_in[1];
    const float* shift = (const float*)d_in[2];
    float* out = (float*)d_out;

    k1_bm_partial<<<64, 1024>>>(X);
    k2_bm_sqrt<<<1, 32>>>();
    k3_logmean<<<NBLK2, 128>>>(X);
    k4a_reduce<<<64, 1024>>>();
    k4_center<<<1, 32>>>(weight);
    k5_center_eig<<<NBLK2, 128>>>(X);
    k6_factor<<<1, 256>>>(shift);
    k7_output<<<NBLK2, 128>>>(out);
}